// round 1
// baseline (speedup 1.0000x reference)
#include <cuda_runtime.h>
#include <cuda_bf16.h>
#include <cstdint>

// ---------------------------------------------------------------------------
// Problem constants
// ---------------------------------------------------------------------------
#define HID   4096
#define LQ    128
#define CTX   896
#define TT    1024          // CTX + LQ
#define STATE 3072
#define SS    4096          // STATE + TT
#define HQ    32
#define HKV   8
#define REP   4
#define DD    128
#define HALF  64
#define EPS   1e-6f
#define SCALE 0.08838834764831845f   // 1/sqrt(128)

// Output layout in d_out (float32): out[128*4096] | k[8*1024*128] | v[8*1024*128]
#define OUT_ELEMS   (LQ * HID)            // 524288
#define K_ELEMS     (HKV * TT * DD)       // 1048576

// ---------------------------------------------------------------------------
// Scratch (device globals: allocation-free, graph-capture safe)
// ---------------------------------------------------------------------------
__device__ float g_qproj[LQ * HQ * DD];          // 524288
__device__ float g_kproj[TT * HKV * DD];         // 1048576
__device__ float g_vproj[TT * HKV * DD];         // 1048576
__device__ float g_qh[HQ * LQ * DD];             // q after norm+rope, head-major
__device__ float g_scores[HQ * LQ * SS];         // 16777216 (64 MB)
__device__ float g_oacc[LQ * HQ * DD];           // attention output, (l, h*128+d)
__device__ float g_part[4 * 1024 * 1024];        // split-K partials (max 4.19M floats)

// ---------------------------------------------------------------------------
// Generic fp32 SGEMM, BM=BN=128, BK=8, TM=TN=8, 256 threads.
//   MODE 0: C_part[kz] = A(two-ptr rows) * B[N,K]^T      (projections, O-proj)
//   MODE 1: C = (A_g * B_g(two-ptr rows)[N,K]^T)*SCALE with causal mask (scores)
//   MODE 2: C_part[g,kz] = A_g * B_g(two-ptr rows)[K,N]  (P * V)
// ---------------------------------------------------------------------------
template <int MODE>
__global__ void __launch_bounds__(256)
gemm_k(const float* __restrict__ Aa, const float* __restrict__ Ab, int Arows1,
       const float* __restrict__ Ba, const float* __restrict__ Bb, int Brows1,
       float* __restrict__ C,
       int M, int N, int K, int splits)
{
    __shared__ float As[8][128];
    __shared__ float Bs[8][128];

    const int tid = threadIdx.x;
    const int bx = blockIdx.x, by = blockIdx.y, bz = blockIdx.z;

    int g = 0, kz = 0;
    if (MODE == 0)      { kz = bz; }
    else if (MODE == 1) { g = bz; }
    else                { g = bz / splits; kz = bz % splits; }

    if (MODE >= 1) {
        Aa += (size_t)g * 512 * K;       // per-kv-head A slab (q heads / scores)
        Ba += (size_t)g * 3072 * 128;    // cache slab
        Bb += (size_t)g * 1024 * 128;    // new-key/value slab
    }

    const int mBase = by * 128;
    const int nBase = bx * 128;
    const int Kc = (MODE == 1) ? K : (K / splits);
    const int k0 = kz * Kc;

    // ---- A fetch indices (A is [M,K], lda = K, rows split Aa/Ab at Arows1)
    const int aRow = tid >> 1;
    const int aCol = (tid & 1) << 2;
    {
        // nothing
    }
    const int gRowA = mBase + aRow;
    const float* arow = (gRowA < Arows1) ? (Aa + (size_t)gRowA * K)
                                         : (Ab + (size_t)(gRowA - Arows1) * K);

    // ---- B fetch indices
    const float* brow = nullptr;
    int bRow = 0, bCol = 0, kbRow = 0, nbCol = 0;
    if (MODE <= 1) {
        bRow = tid >> 1; bCol = (tid & 1) << 2;
        const int gN = nBase + bRow;
        brow = (gN < Brows1) ? (Ba + (size_t)gN * K)
                             : (Bb + (size_t)(gN - Brows1) * K);
    } else {
        kbRow = tid >> 5;            // 0..7
        nbCol = (tid & 31) << 2;     // 0..124
    }

    float acc[8][8];
    #pragma unroll
    for (int i = 0; i < 8; i++)
        #pragma unroll
        for (int j = 0; j < 8; j++) acc[i][j] = 0.f;

    const int tx = tid & 15, ty = tid >> 4;

    for (int kk = k0; kk < k0 + Kc; kk += 8) {
        float4 av = *(const float4*)(arow + kk + aCol);
        As[aCol + 0][aRow] = av.x;
        As[aCol + 1][aRow] = av.y;
        As[aCol + 2][aRow] = av.z;
        As[aCol + 3][aRow] = av.w;

        if (MODE <= 1) {
            float4 bv = *(const float4*)(brow + kk + bCol);
            Bs[bCol + 0][bRow] = bv.x;
            Bs[bCol + 1][bRow] = bv.y;
            Bs[bCol + 2][bRow] = bv.z;
            Bs[bCol + 3][bRow] = bv.w;
        } else {
            const int gK = kk + kbRow;
            const float* br = (gK < Brows1) ? (Ba + (size_t)gK * 128)
                                            : (Bb + (size_t)(gK - Brows1) * 128);
            *(float4*)&Bs[kbRow][nbCol] = *(const float4*)(br + nBase + nbCol);
        }
        __syncthreads();

        #pragma unroll
        for (int k = 0; k < 8; k++) {
            float a[8], b[8];
            *(float4*)&a[0] = *(const float4*)&As[k][ty * 8];
            *(float4*)&a[4] = *(const float4*)&As[k][ty * 8 + 4];
            *(float4*)&b[0] = *(const float4*)&Bs[k][tx * 8];
            *(float4*)&b[4] = *(const float4*)&Bs[k][tx * 8 + 4];
            #pragma unroll
            for (int i = 0; i < 8; i++)
                #pragma unroll
                for (int j = 0; j < 8; j++)
                    acc[i][j] += a[i] * b[j];
        }
        __syncthreads();
    }

    // ---- epilogue
    if (MODE == 0) {
        float* Cp = C + (size_t)kz * M * N;
        #pragma unroll
        for (int i = 0; i < 8; i++) {
            const int row = mBase + ty * 8 + i;
            float* cr = Cp + (size_t)row * N + nBase + tx * 8;
            *(float4*)cr       = make_float4(acc[i][0], acc[i][1], acc[i][2], acc[i][3]);
            *(float4*)(cr + 4) = make_float4(acc[i][4], acc[i][5], acc[i][6], acc[i][7]);
        }
    } else if (MODE == 1) {
        float* Cp = C + (size_t)g * M * N;
        #pragma unroll
        for (int i = 0; i < 8; i++) {
            const int row = mBase + ty * 8 + i;
            const int l = row & 127;
            float* cr = Cp + (size_t)row * N + nBase + tx * 8;
            #pragma unroll
            for (int j = 0; j < 8; j++) {
                float v = acc[i][j] * SCALE;
                if (nBase + tx * 8 + j > 3968 + l) v = -1e30f;
                cr[j] = v;
            }
        }
    } else {
        float* Cp = C + ((size_t)(g * splits + kz)) * M * N;
        #pragma unroll
        for (int i = 0; i < 8; i++) {
            const int row = mBase + ty * 8 + i;
            float* cr = Cp + (size_t)row * N + nBase + tx * 8;
            *(float4*)cr       = make_float4(acc[i][0], acc[i][1], acc[i][2], acc[i][3]);
            *(float4*)(cr + 4) = make_float4(acc[i][4], acc[i][5], acc[i][6], acc[i][7]);
        }
    }
}

// ---------------------------------------------------------------------------
// Split-K reductions (deterministic)
// ---------------------------------------------------------------------------
__global__ void reduce_sum(const float* __restrict__ part, float* __restrict__ C,
                           int MN, int splits)
{
    const int i = blockIdx.x * 256 + threadIdx.x;
    if (i < MN) {
        float s = 0.f;
        for (int z = 0; z < splits; z++) s += part[(size_t)z * MN + i];
        C[i] = s;
    }
}

// part layout: [(g*8+kz)][512][128] -> g_oacc[l*4096 + h*128 + n]
__global__ void reduce_o(const float* __restrict__ part, float* __restrict__ o)
{
    const int i = blockIdx.x * 256 + threadIdx.x;   // 0 .. 524287
    const int g = i >> 16;
    const int rem = i & 65535;
    const int m = rem >> 7;
    const int n = rem & 127;
    float s = 0.f;
    #pragma unroll
    for (int z = 0; z < 8; z++)
        s += part[(((size_t)(g * 8 + z)) << 16) + rem];
    const int h = g * 4 + (m >> 7);
    const int l = m & 127;
    o[(size_t)l * 4096 + h * 128 + n] = s;
}

// ---------------------------------------------------------------------------
// Row softmax over 4096 cols (in-place, masked entries are -1e30 -> exp = 0)
// ---------------------------------------------------------------------------
__global__ void __launch_bounds__(256) softmax_k(float* __restrict__ scores)
{
    __shared__ float red[256];
    const int row = blockIdx.x;
    float* p = scores + (size_t)row * 4096;
    const int tid = threadIdx.x;

    float v[16];
    float mx = -1e30f;
    #pragma unroll
    for (int i = 0; i < 16; i++) {
        v[i] = p[tid + i * 256];
        mx = fmaxf(mx, v[i]);
    }
    red[tid] = mx; __syncthreads();
    #pragma unroll
    for (int s = 128; s > 0; s >>= 1) {
        if (tid < s) red[tid] = fmaxf(red[tid], red[tid + s]);
        __syncthreads();
    }
    mx = red[0]; __syncthreads();

    float sum = 0.f;
    #pragma unroll
    for (int i = 0; i < 16; i++) {
        v[i] = expf(v[i] - mx);
        sum += v[i];
    }
    red[tid] = sum; __syncthreads();
    #pragma unroll
    for (int s = 128; s > 0; s >>= 1) {
        if (tid < s) red[tid] += red[tid + s];
        __syncthreads();
    }
    const float inv = 1.f / red[0];
    #pragma unroll
    for (int i = 0; i < 16; i++) p[tid + i * 256] = v[i] * inv;
}

// ---------------------------------------------------------------------------
// ane-norm + RoPE + transpose.  Block = one (row, head) of 128 dims.
//  blocks [0, 4096)        : q rows -> g_qh[h][l][d]
//  blocks [4096, 12288)    : k rows -> out_k[g][t][d]   (norm + rope)
//  blocks [12288, 20480)   : v rows -> out_v[g][t][d]   (transpose only)
// ---------------------------------------------------------------------------
__device__ __forceinline__ float block_sum_128(float v, float* red, int d)
{
    red[d] = v; __syncthreads();
    #pragma unroll
    for (int s = 64; s > 0; s >>= 1) {
        if (d < s) red[d] += red[d + s];
        __syncthreads();
    }
    float r = red[0]; __syncthreads();
    return r;
}

__global__ void __launch_bounds__(128)
norm_rope_k(const float* __restrict__ qproj, const float* __restrict__ kproj,
            const float* __restrict__ vproj,
            const float* __restrict__ cos_q, const float* __restrict__ sin_q,
            const float* __restrict__ cos_k, const float* __restrict__ sin_k,
            const float* __restrict__ qw, const float* __restrict__ kw,
            float* __restrict__ qh, float* __restrict__ out_k, float* __restrict__ out_v)
{
    __shared__ float red[128];
    __shared__ float y[128];
    const int b = blockIdx.x;
    const int d = threadIdx.x;

    if (b < LQ * HQ) {
        const int l = b / HQ, h = b % HQ;
        const float x = qproj[(size_t)l * 4096 + h * 128 + d];
        const float mean = block_sum_128(x, red, d) * (1.f / 128.f);
        const float xc = x - mean;
        const float var = block_sum_128(xc * xc, red, d) * (1.f / 128.f);
        const float yn = xc * rsqrtf(var + EPS) * qw[d];
        y[d] = yn; __syncthreads();
        const float rot = (d < HALF) ? -y[d + HALF] : y[d - HALF];
        const float o = yn * cos_q[l * 128 + d] + rot * sin_q[l * 128 + d];
        qh[((size_t)h * LQ + l) * 128 + d] = o;
    } else if (b < LQ * HQ + TT * HKV) {
        const int idx = b - LQ * HQ;
        const int t = idx / HKV, g = idx % HKV;
        const float x = kproj[(size_t)t * 1024 + g * 128 + d];
        const float mean = block_sum_128(x, red, d) * (1.f / 128.f);
        const float xc = x - mean;
        const float var = block_sum_128(xc * xc, red, d) * (1.f / 128.f);
        const float yn = xc * rsqrtf(var + EPS) * kw[d];
        y[d] = yn; __syncthreads();
        const float rot = (d < HALF) ? -y[d + HALF] : y[d - HALF];
        const float o = yn * cos_k[t * 128 + d] + rot * sin_k[t * 128 + d];
        out_k[((size_t)g * TT + t) * 128 + d] = o;
    } else {
        const int idx = b - LQ * HQ - TT * HKV;
        const int t = idx / HKV, g = idx % HKV;
        out_v[((size_t)g * TT + t) * 128 + d] = vproj[(size_t)t * 1024 + g * 128 + d];
    }
}

// ---------------------------------------------------------------------------
// Launch
// ---------------------------------------------------------------------------
extern "C" void kernel_launch(void* const* d_in, const int* in_sizes, int n_in,
                              void* d_out, int out_size)
{
    const float* x      = (const float*)d_in[0];
    const float* x_ctx  = (const float*)d_in[1];
    const float* cos_q  = (const float*)d_in[2];
    const float* sin_q  = (const float*)d_in[3];
    const float* cos_k  = (const float*)d_in[4];
    const float* sin_k  = (const float*)d_in[5];
    const float* cacheK = (const float*)d_in[6];
    const float* cacheV = (const float*)d_in[7];
    // d_in[8] = causal_mask (bool) -- mask is computed analytically, ignored
    const float* Wq     = (const float*)d_in[9];
    const float* Wk     = (const float*)d_in[10];
    const float* Wv     = (const float*)d_in[11];
    const float* Wo     = (const float*)d_in[12];
    const float* qw     = (const float*)d_in[13];
    const float* kw     = (const float*)d_in[14];

    float* out   = (float*)d_out;
    float* out_k = out + OUT_ELEMS;
    float* out_v = out_k + K_ELEMS;

    float *p_qproj, *p_kproj, *p_vproj, *p_qh, *p_scores, *p_oacc, *p_part;
    cudaGetSymbolAddress((void**)&p_qproj,  g_qproj);
    cudaGetSymbolAddress((void**)&p_kproj,  g_kproj);
    cudaGetSymbolAddress((void**)&p_vproj,  g_vproj);
    cudaGetSymbolAddress((void**)&p_qh,     g_qh);
    cudaGetSymbolAddress((void**)&p_scores, g_scores);
    cudaGetSymbolAddress((void**)&p_oacc,   g_oacc);
    cudaGetSymbolAddress((void**)&p_part,   g_part);

    const int BIG = 1 << 30;

    // 1) Q projection: (128 x 4096) = x * Wq^T, split-K=4
    gemm_k<0><<<dim3(32, 1, 4), 256>>>(x, x, BIG, Wq, Wq, BIG,
                                       p_part, 128, 4096, 4096, 4);
    reduce_sum<<<OUT_ELEMS / 256, 256>>>(p_part, p_qproj, OUT_ELEMS, 4);

    // 2) K projection: (1024 x 1024) = [x_ctx; x] * Wk^T, split-K=2
    gemm_k<0><<<dim3(8, 8, 2), 256>>>(x_ctx, x, CTX, Wk, Wk, BIG,
                                      p_part, 1024, 1024, 4096, 2);
    reduce_sum<<<K_ELEMS / 256, 256>>>(p_part, p_kproj, K_ELEMS, 2);

    // 3) V projection
    gemm_k<0><<<dim3(8, 8, 2), 256>>>(x_ctx, x, CTX, Wv, Wv, BIG,
                                      p_part, 1024, 1024, 4096, 2);
    reduce_sum<<<K_ELEMS / 256, 256>>>(p_part, p_vproj, K_ELEMS, 2);

    // 4) norm + rope + transpose (also writes k/v outputs)
    norm_rope_k<<<LQ * HQ + 2 * TT * HKV, 128>>>(
        p_qproj, p_kproj, p_vproj, cos_q, sin_q, cos_k, sin_k, qw, kw,
        p_qh, out_k, out_v);

    // 5) scores: per kv-head g, (512 x 4096) = Qg * [cacheK_g; k_new_g]^T
    //    epilogue: * SCALE, causal mask (col > 3968 + l -> -1e30)
    gemm_k<1><<<dim3(32, 4, 8), 256>>>(p_qh, p_qh, BIG, cacheK, out_k, STATE,
                                       p_scores, 512, 4096, 128, 1);

    // 6) softmax over 4096 keys, in place
    softmax_k<<<HQ * LQ, 256>>>(p_scores);

    // 7) O = P * V: per g, (512 x 128), split-K=8
    gemm_k<2><<<dim3(1, 4, 64), 256>>>(p_scores, p_scores, BIG, cacheV, out_v, STATE,
                                       p_part, 512, 128, 4096, 8);
    reduce_o<<<OUT_ELEMS / 256, 256>>>(p_part, p_oacc);

    // 8) final projection: (128 x 4096) = o * Wo^T, split-K=4
    gemm_k<0><<<dim3(32, 1, 4), 256>>>(p_oacc, p_oacc, BIG, Wo, Wo, BIG,
                                       p_part, 128, 4096, 4096, 4);
    reduce_sum<<<OUT_ELEMS / 256, 256>>>(p_part, out, OUT_ELEMS, 4);
}